// round 1
// baseline (speedup 1.0000x reference)
#include <cuda_runtime.h>
#include <cuda_bf16.h>

// QRegulariser: out = mean_b( 1 - prod_q cos^2( (hidden@W.T + b)_q / 2 ) )
// B=65536, H=1024, Q=8. Pure HBM-bound (256 MB of hidden, 1.1 GFLOP).
//
// Layout: warp processes 8 rows; lane loads float4 at col = it*128 + lane*4
// (fully coalesced 512B per LDG.128 per warp). W staged in shared (32 KB),
// read as float4 (lane-consecutive -> conflict-free). 8 q-accumulators x
// 8 rows per lane, butterfly-reduced over the warp at the end (amortized
// over 8 rows -> SHFL cost ~1.25 issue slots / 128B of HBM).

#define HDIM 1024
#define QDIM 8
#define ROWS_PER_WARP 8
#define WARPS_PER_BLOCK 8
#define NTHREADS (WARPS_PER_BLOCK * 32)
#define ROWS_PER_BLOCK (ROWS_PER_WARP * WARPS_PER_BLOCK)

__device__ double g_qreg_sum;

__global__ void qreg_zero_kernel() {
    g_qreg_sum = 0.0;
}

__global__ __launch_bounds__(NTHREADS, 2)
void qreg_main_kernel(const float* __restrict__ hidden,
                      const float* __restrict__ Wm,
                      const float* __restrict__ bv,
                      int B) {
    __shared__ float sW[QDIM * HDIM];           // 32 KB
    __shared__ float sB[QDIM];
    __shared__ double warp_sums[WARPS_PER_BLOCK];

    const int tid = threadIdx.x;

    // Stage W (coalesced) and b into shared.
    #pragma unroll 4
    for (int i = tid; i < QDIM * HDIM; i += NTHREADS) sW[i] = Wm[i];
    if (tid < QDIM) sB[tid] = bv[tid];
    __syncthreads();

    const int warp = tid >> 5;
    const int lane = tid & 31;
    const int row0 = blockIdx.x * ROWS_PER_BLOCK + warp * ROWS_PER_WARP;

    float acc[ROWS_PER_WARP][QDIM];
    #pragma unroll
    for (int r = 0; r < ROWS_PER_WARP; ++r)
        #pragma unroll
        for (int q = 0; q < QDIM; ++q)
            acc[r][q] = 0.0f;

    const float4* __restrict__ h4 = reinterpret_cast<const float4*>(hidden);
    const float4* __restrict__ w4 = reinterpret_cast<const float4*>(sW);
    const int row_stride4 = HDIM / 4;  // 256 float4 per row

    #pragma unroll
    for (int it = 0; it < HDIM / 128; ++it) {
        const int col4 = it * 32 + lane;  // float4 column index

        // Front-batched loads: 8 independent LDG.128 in flight per warp.
        float4 h[ROWS_PER_WARP];
        #pragma unroll
        for (int r = 0; r < ROWS_PER_WARP; ++r) {
            const int row = row0 + r;
            if (row < B) {
                h[r] = h4[(long long)row * row_stride4 + col4];
            } else {
                h[r] = make_float4(0.f, 0.f, 0.f, 0.f);
            }
        }

        #pragma unroll
        for (int q = 0; q < QDIM; ++q) {
            const float4 w = w4[q * row_stride4 + col4];
            #pragma unroll
            for (int r = 0; r < ROWS_PER_WARP; ++r) {
                acc[r][q] = fmaf(h[r].x, w.x, acc[r][q]);
                acc[r][q] = fmaf(h[r].y, w.y, acc[r][q]);
                acc[r][q] = fmaf(h[r].z, w.z, acc[r][q]);
                acc[r][q] = fmaf(h[r].w, w.w, acc[r][q]);
            }
        }
    }

    // Butterfly-reduce every accumulator across the warp: after this,
    // every lane holds the full dot product for all (row, q).
    #pragma unroll
    for (int r = 0; r < ROWS_PER_WARP; ++r) {
        #pragma unroll
        for (int q = 0; q < QDIM; ++q) {
            float v = acc[r][q];
            v += __shfl_xor_sync(0xffffffffu, v, 16);
            v += __shfl_xor_sync(0xffffffffu, v, 8);
            v += __shfl_xor_sync(0xffffffffu, v, 4);
            v += __shfl_xor_sync(0xffffffffu, v, 2);
            v += __shfl_xor_sync(0xffffffffu, v, 1);
            acc[r][q] = v;
        }
    }

    // Redundant epilogue in all lanes (cheap): p0 = prod (1+cos theta)/2.
    double local = 0.0;
    #pragma unroll
    for (int r = 0; r < ROWS_PER_WARP; ++r) {
        const int row = row0 + r;
        float p = 1.0f;
        #pragma unroll
        for (int q = 0; q < QDIM; ++q) {
            const float th = acc[r][q] + sB[q];
            p *= 0.5f * (1.0f + __cosf(th));
        }
        if (row < B) local += (double)(1.0f - p);
    }

    if (lane == 0) warp_sums[warp] = local;
    __syncthreads();

    if (tid == 0) {
        double s = 0.0;
        #pragma unroll
        for (int w = 0; w < WARPS_PER_BLOCK; ++w) s += warp_sums[w];
        atomicAdd(&g_qreg_sum, s);
    }
}

__global__ void qreg_finalize_kernel(float* __restrict__ out, int B) {
    out[0] = (float)(g_qreg_sum / (double)B);
}

extern "C" void kernel_launch(void* const* d_in, const int* in_sizes, int n_in,
                              void* d_out, int out_size) {
    const float* hidden = (const float*)d_in[0];   // [B, H] f32
    const float* Wm     = (const float*)d_in[1];   // [Q, H] f32
    const float* bv     = (const float*)d_in[2];   // [Q]    f32
    float* out = (float*)d_out;

    const int B = in_sizes[0] / HDIM;

    qreg_zero_kernel<<<1, 1>>>();

    const int grid = (B + ROWS_PER_BLOCK - 1) / ROWS_PER_BLOCK;
    qreg_main_kernel<<<grid, NTHREADS>>>(hidden, Wm, bv, B);

    qreg_finalize_kernel<<<1, 1>>>(out, B);
}

// round 2
// speedup vs baseline: 1.3504x; 1.3504x over previous
#include <cuda_runtime.h>
#include <cuda_bf16.h>
#include <cstdint>

// QRegulariser: out = mean_b( 1 - prod_q cos^2( (hidden@W.T + b)_q / 2 ) )
// B=65536, H=1024, Q=8. HBM-bound: 256 MB of hidden.
//
// R2 changes vs R1 (87us main kernel):
//  - k-loop kept ROLLED (R1's full unroll spilled accumulators to local)
//  - packed fma.rn.f32x2 with q-pairing: W stored transposed in shared as
//    32B-per-column q-vectors (adjacent floats = f32x2 pairs, no w packing),
//    SW128-swizzled for conflict-free LDS.128. Halves FMA-pipe pressure.
//  - no zero kernel: per-block partials + finalize reduction.

#define HDIM 1024
#define QDIM 8
#define ROWS_PER_WARP 8
#define WARPS_PER_BLOCK 8
#define NTHREADS 256
#define ROWS_PER_BLOCK (ROWS_PER_WARP * WARPS_PER_BLOCK)
#define MAX_BLOCKS 8192

__device__ double g_partials[MAX_BLOCKS];

__device__ __forceinline__ uint32_t swz(uint32_t off) {
    // SW128 swizzle: XOR addr bits [7:9] into [4:6]
    return off ^ ((off >> 3) & 0x70u);
}

__device__ __forceinline__ unsigned long long fma2(unsigned long long a,
                                                   unsigned long long b,
                                                   unsigned long long c) {
    unsigned long long d;
    asm("fma.rn.f32x2 %0, %1, %2, %3;" : "=l"(d) : "l"(a), "l"(b), "l"(c));
    return d;
}
__device__ __forceinline__ unsigned long long add2(unsigned long long a,
                                                   unsigned long long b) {
    unsigned long long d;
    asm("add.rn.f32x2 %0, %1, %2;" : "=l"(d) : "l"(a), "l"(b));
    return d;
}
__device__ __forceinline__ unsigned long long packff(float x) {
    unsigned long long d;
    asm("mov.b64 %0, {%1, %1};" : "=l"(d) : "f"(x));
    return d;
}
__device__ __forceinline__ float2 unpack2(unsigned long long v) {
    float2 r;
    asm("mov.b64 {%0, %1}, %2;" : "=f"(r.x), "=f"(r.y) : "l"(v));
    return r;
}

// Per-warp worker: 8 rows, full H sweep, returns sum of (1 - p0) over valid rows.
template <bool GUARD>
__device__ __forceinline__ double warp_rows(const float4* __restrict__ h4,
                                            const char* __restrict__ sW,
                                            const float* __restrict__ sB,
                                            int row0, int B, int lane) {
    unsigned long long acc[ROWS_PER_WARP][4];  // (q0,q1)(q2,q3)(q4,q5)(q6,q7) pairs
    #pragma unroll
    for (int r = 0; r < ROWS_PER_WARP; ++r)
        #pragma unroll
        for (int qp = 0; qp < 4; ++qp)
            acc[r][qp] = 0ull;

    #pragma unroll 1
    for (int it = 0; it < HDIM / 128; ++it) {
        const int col4 = it * 32 + lane;  // float4 column index

        // Front-batched: 8 independent LDG.128 in flight.
        float4 h[ROWS_PER_WARP];
        #pragma unroll
        for (int r = 0; r < ROWS_PER_WARP; ++r) {
            if (!GUARD || (row0 + r) < B)
                h[r] = h4[(size_t)(row0 + r) * (HDIM / 4) + col4];
            else
                h[r] = make_float4(0.f, 0.f, 0.f, 0.f);
        }

        #pragma unroll
        for (int j = 0; j < 4; ++j) {
            // element index e = col4*4 + j; W^T bytes at e*32
            const uint32_t base = (uint32_t)col4 * 128u + (uint32_t)j * 32u;
            const ulonglong2 wA = *reinterpret_cast<const ulonglong2*>(sW + swz(base));
            const ulonglong2 wB = *reinterpret_cast<const ulonglong2*>(sW + swz(base + 16u));

            #pragma unroll
            for (int r = 0; r < ROWS_PER_WARP; ++r) {
                const float* hp = &h[r].x;
                const unsigned long long hh = packff(hp[j]);
                acc[r][0] = fma2(hh, wA.x, acc[r][0]);
                acc[r][1] = fma2(hh, wA.y, acc[r][1]);
                acc[r][2] = fma2(hh, wB.x, acc[r][2]);
                acc[r][3] = fma2(hh, wB.y, acc[r][3]);
            }
        }
    }

    // Butterfly-reduce each pair across the warp (2 SHFL + 1 add2 per step).
    #pragma unroll
    for (int r = 0; r < ROWS_PER_WARP; ++r) {
        #pragma unroll
        for (int qp = 0; qp < 4; ++qp) {
            unsigned long long v = acc[r][qp];
            #pragma unroll
            for (int d = 16; d > 0; d >>= 1)
                v = add2(v, __shfl_xor_sync(0xffffffffu, v, d));
            acc[r][qp] = v;
        }
    }

    // Redundant epilogue in all lanes.
    double local = 0.0;
    #pragma unroll
    for (int r = 0; r < ROWS_PER_WARP; ++r) {
        if (GUARD && (row0 + r) >= B) continue;
        float p = 1.0f;
        #pragma unroll
        for (int qp = 0; qp < 4; ++qp) {
            const float2 th = unpack2(acc[r][qp]);
            const float t0 = th.x + sB[2 * qp];
            const float t1 = th.y + sB[2 * qp + 1];
            p *= 0.25f * (1.0f + __cosf(t0)) * (1.0f + __cosf(t1));
        }
        local += (double)(1.0f - p);
    }
    return local;
}

__global__ __launch_bounds__(NTHREADS, 2)
void qreg_main_kernel(const float* __restrict__ hidden,
                      const float* __restrict__ Wm,
                      const float* __restrict__ bv,
                      int B) {
    __shared__ __align__(128) char sW[QDIM * HDIM * 4];  // 32 KB, W^T pair layout, swizzled
    __shared__ float sB[QDIM];
    __shared__ double warp_sums[WARPS_PER_BLOCK];

    const int tid = threadIdx.x;

    // Build swizzled W^T: column c gets 32 bytes (q0..q7 floats) at off = c*32 + q*4.
    // Read W coalesced as float4 (i covers q=(4i)/H, c=(4i)%H .. +3), scatter to shared.
    for (int i = tid; i < QDIM * HDIM / 4; i += NTHREADS) {
        const float4 v = reinterpret_cast<const float4*>(Wm)[i];
        const int q = (i * 4) / HDIM;
        const int c = (i * 4) % HDIM;
        const float vv[4] = {v.x, v.y, v.z, v.w};
        #pragma unroll
        for (int j = 0; j < 4; ++j) {
            const uint32_t off = swz((uint32_t)(c + j) * 32u + (uint32_t)q * 4u);
            *reinterpret_cast<float*>(sW + off) = vv[j];
        }
    }
    if (tid < QDIM) sB[tid] = bv[tid];
    __syncthreads();

    const int warp = tid >> 5;
    const int lane = tid & 31;
    const int row0 = blockIdx.x * ROWS_PER_BLOCK + warp * ROWS_PER_WARP;

    const float4* h4 = reinterpret_cast<const float4*>(hidden);

    double local;
    if (row0 + ROWS_PER_WARP <= B)
        local = warp_rows<false>(h4, sW, sB, row0, B, lane);
    else
        local = warp_rows<true>(h4, sW, sB, row0, B, lane);

    if (lane == 0) warp_sums[warp] = local;
    __syncthreads();

    if (tid == 0) {
        double s = 0.0;
        #pragma unroll
        for (int w = 0; w < WARPS_PER_BLOCK; ++w) s += warp_sums[w];
        g_partials[blockIdx.x] = s;
    }
}

__global__ void qreg_finalize_kernel(float* __restrict__ out, int nblocks, int B) {
    __shared__ double ws[8];
    const int tid = threadIdx.x;
    double s = 0.0;
    for (int i = tid; i < nblocks; i += 256) s += g_partials[i];
    #pragma unroll
    for (int d = 16; d > 0; d >>= 1) s += __shfl_down_sync(0xffffffffu, s, d);
    if ((tid & 31) == 0) ws[tid >> 5] = s;
    __syncthreads();
    if (tid == 0) {
        double t = 0.0;
        #pragma unroll
        for (int w = 0; w < 8; ++w) t += ws[w];
        out[0] = (float)(t / (double)B);
    }
}

extern "C" void kernel_launch(void* const* d_in, const int* in_sizes, int n_in,
                              void* d_out, int out_size) {
    const float* hidden = (const float*)d_in[0];   // [B, H] f32
    const float* Wm     = (const float*)d_in[1];   // [Q, H] f32
    const float* bv     = (const float*)d_in[2];   // [Q]    f32
    float* out = (float*)d_out;

    const int B = in_sizes[0] / HDIM;
    int grid = (B + ROWS_PER_BLOCK - 1) / ROWS_PER_BLOCK;
    if (grid > MAX_BLOCKS) grid = MAX_BLOCKS;  // B fixed at 65536 -> 1024 blocks

    qreg_main_kernel<<<grid, NTHREADS>>>(hidden, Wm, bv, B);
    qreg_finalize_kernel<<<1, 256>>>(out, grid, B);
}

// round 3
// speedup vs baseline: 1.6372x; 1.2124x over previous
#include <cuda_runtime.h>
#include <cuda_bf16.h>
#include <cstdint>

// QRegulariser: out = mean_b( 1 - prod_q cos^2( (hidden@W.T + b)_q / 2 ) )
// B=65536, H=1024, Q=8. HBM-bound: 256 MB of hidden.
//
// R3 changes vs R2 (65us main):
//  - 4 rows/warp + double-buffered prefetch: next iteration's LDG.128s are in
//    flight during current compute (continuous MLP; R2 exposed ~600cyc DRAM
//    latency every iteration). Regs ~95 (was ~125, at the 128 cap).
//  - persistent grid (296 CTAs) + grid-stride tile loop: no wave quantization.
//  - finalize fused into main kernel (atomic-counter last-block pattern).

#define HDIM 1024
#define QDIM 8
#define RPW 4                      // rows per warp per tile
#define WPB 8                      // warps per block
#define NTHREADS 256
#define TILE_ROWS (RPW * WPB)      // 32
#define GRID_MAX 296               // 148 SMs * occupancy 2

__device__ double g_partials[GRID_MAX];
__device__ unsigned int g_counter = 0;

__device__ __forceinline__ uint32_t swz(uint32_t off) {
    return off ^ ((off >> 3) & 0x70u);  // SW128: XOR bits[7:9] into [4:6]
}
__device__ __forceinline__ unsigned long long fma2(unsigned long long a,
                                                   unsigned long long b,
                                                   unsigned long long c) {
    unsigned long long d;
    asm("fma.rn.f32x2 %0, %1, %2, %3;" : "=l"(d) : "l"(a), "l"(b), "l"(c));
    return d;
}
__device__ __forceinline__ unsigned long long add2(unsigned long long a,
                                                   unsigned long long b) {
    unsigned long long d;
    asm("add.rn.f32x2 %0, %1, %2;" : "=l"(d) : "l"(a), "l"(b));
    return d;
}
__device__ __forceinline__ unsigned long long packff(float x) {
    unsigned long long d;
    asm("mov.b64 %0, {%1, %1};" : "=l"(d) : "f"(x));
    return d;
}
__device__ __forceinline__ float2 unpack2(unsigned long long v) {
    float2 r;
    asm("mov.b64 {%0, %1}, %2;" : "=f"(r.x), "=f"(r.y) : "l"(v));
    return r;
}

// One 128-element chunk of the dot products: h[RPW] float4s at column block
// `it`, accumulating q-pairs. W^T in shared: column c holds 32B (q0..q7).
__device__ __forceinline__ void compute_chunk(const float4 (&h)[RPW],
                                              unsigned long long (&acc)[RPW][4],
                                              const char* __restrict__ sW,
                                              int it, int lane) {
    const int col4 = it * 32 + lane;
    #pragma unroll
    for (int j = 0; j < 4; ++j) {
        const uint32_t base = (uint32_t)col4 * 128u + (uint32_t)j * 32u;
        const ulonglong2 wA = *reinterpret_cast<const ulonglong2*>(sW + swz(base));
        const ulonglong2 wB = *reinterpret_cast<const ulonglong2*>(sW + swz(base + 16u));
        #pragma unroll
        for (int r = 0; r < RPW; ++r) {
            const float* hp = &h[r].x;
            const unsigned long long hh = packff(hp[j]);
            acc[r][0] = fma2(hh, wA.x, acc[r][0]);
            acc[r][1] = fma2(hh, wA.y, acc[r][1]);
            acc[r][2] = fma2(hh, wB.x, acc[r][2]);
            acc[r][3] = fma2(hh, wB.y, acc[r][3]);
        }
    }
}

template <bool GUARD>
__device__ __forceinline__ double warp_tile(const float4* __restrict__ h4,
                                            const char* __restrict__ sW,
                                            const float* __restrict__ sB,
                                            int row0, int B, int lane) {
    unsigned long long acc[RPW][4];
    #pragma unroll
    for (int r = 0; r < RPW; ++r)
        #pragma unroll
        for (int qp = 0; qp < 4; ++qp) acc[r][qp] = 0ull;

    const float4* p[RPW];
    #pragma unroll
    for (int r = 0; r < RPW; ++r)
        p[r] = h4 + (size_t)(row0 + r) * (HDIM / 4) + lane;

    const float4 z4 = make_float4(0.f, 0.f, 0.f, 0.f);

    float4 hA[RPW], hB[RPW];
    #pragma unroll
    for (int r = 0; r < RPW; ++r)
        hA[r] = (!GUARD || (row0 + r) < B) ? p[r][0] : z4;

    #pragma unroll 1
    for (int it = 0; it < HDIM / 128; it += 2) {
        // Prefetch it+1 (in flight during compute of it).
        #pragma unroll
        for (int r = 0; r < RPW; ++r)
            hB[r] = (!GUARD || (row0 + r) < B) ? p[r][(it + 1) * 32] : z4;

        compute_chunk(hA, acc, sW, it, lane);

        // Prefetch it+2 (in flight during compute of it+1).
        if (it + 2 < HDIM / 128) {
            #pragma unroll
            for (int r = 0; r < RPW; ++r)
                hA[r] = (!GUARD || (row0 + r) < B) ? p[r][(it + 2) * 32] : z4;
        }

        compute_chunk(hB, acc, sW, it + 1, lane);
    }

    // Butterfly-reduce each q-pair across the warp (all lanes end with totals).
    #pragma unroll
    for (int r = 0; r < RPW; ++r) {
        #pragma unroll
        for (int qp = 0; qp < 4; ++qp) {
            unsigned long long v = acc[r][qp];
            #pragma unroll
            for (int d = 16; d > 0; d >>= 1)
                v = add2(v, __shfl_xor_sync(0xffffffffu, v, d));
            acc[r][qp] = v;
        }
    }

    // Redundant epilogue in all lanes: p0 = prod_q (1+cos theta_q)/2.
    double local = 0.0;
    #pragma unroll
    for (int r = 0; r < RPW; ++r) {
        if (GUARD && (row0 + r) >= B) continue;
        float pr = 1.0f;
        #pragma unroll
        for (int qp = 0; qp < 4; ++qp) {
            const float2 th = unpack2(acc[r][qp]);
            const float t0 = th.x + sB[2 * qp];
            const float t1 = th.y + sB[2 * qp + 1];
            pr *= 0.25f * (1.0f + __cosf(t0)) * (1.0f + __cosf(t1));
        }
        local += (double)(1.0f - pr);
    }
    return local;
}

__global__ __launch_bounds__(NTHREADS, 2)
void qreg_main_kernel(const float* __restrict__ hidden,
                      const float* __restrict__ Wm,
                      const float* __restrict__ bv,
                      float* __restrict__ out,
                      int B) {
    __shared__ __align__(128) char sW[QDIM * HDIM * 4];  // 32 KB swizzled W^T
    __shared__ float sB[QDIM];
    __shared__ double warp_sums[WPB];
    __shared__ unsigned int is_last;

    const int tid = threadIdx.x;

    // Build swizzled W^T: column c gets 32B (q0..q7) at off = c*32 + q*4.
    for (int i = tid; i < QDIM * HDIM / 4; i += NTHREADS) {
        const float4 v = reinterpret_cast<const float4*>(Wm)[i];
        const int q = (i * 4) / HDIM;
        const int c = (i * 4) % HDIM;
        const float vv[4] = {v.x, v.y, v.z, v.w};
        #pragma unroll
        for (int j = 0; j < 4; ++j) {
            const uint32_t off = swz((uint32_t)(c + j) * 32u + (uint32_t)q * 4u);
            *reinterpret_cast<float*>(sW + off) = vv[j];
        }
    }
    if (tid < QDIM) sB[tid] = bv[tid];
    __syncthreads();

    const int warp = tid >> 5;
    const int lane = tid & 31;
    const float4* h4 = reinterpret_cast<const float4*>(hidden);
    const int ntiles = (B + TILE_ROWS - 1) / TILE_ROWS;

    double local = 0.0;
    for (int t = blockIdx.x; t < ntiles; t += gridDim.x) {
        const int row0 = t * TILE_ROWS + warp * RPW;
        if (row0 + RPW <= B)
            local += warp_tile<false>(h4, sW, sB, row0, B, lane);
        else if (row0 < B)
            local += warp_tile<true>(h4, sW, sB, row0, B, lane);
    }

    if (lane == 0) warp_sums[warp] = local;
    __syncthreads();

    if (tid == 0) {
        double s = 0.0;
        #pragma unroll
        for (int w = 0; w < WPB; ++w) s += warp_sums[w];
        g_partials[blockIdx.x] = s;
        __threadfence();
        const unsigned int prev = atomicAdd(&g_counter, 1u);
        is_last = (prev == gridDim.x - 1) ? 1u : 0u;
    }
    __syncthreads();

    // Last block to finish reduces all partials and writes the output.
    if (is_last) {
        __threadfence();
        const volatile double* vp = g_partials;
        double s = 0.0;
        for (int i = tid; i < (int)gridDim.x; i += NTHREADS) s += vp[i];
        #pragma unroll
        for (int d = 16; d > 0; d >>= 1)
            s += __shfl_down_sync(0xffffffffu, s, d);
        if (lane == 0) warp_sums[warp] = s;
        __syncthreads();
        if (tid == 0) {
            double tsum = 0.0;
            #pragma unroll
            for (int w = 0; w < WPB; ++w) tsum += warp_sums[w];
            out[0] = (float)(tsum / (double)B);
            g_counter = 0;  // reset for the next (graph-replayed) call
        }
    }
}

extern "C" void kernel_launch(void* const* d_in, const int* in_sizes, int n_in,
                              void* d_out, int out_size) {
    const float* hidden = (const float*)d_in[0];   // [B, H] f32
    const float* Wm     = (const float*)d_in[1];   // [Q, H] f32
    const float* bv     = (const float*)d_in[2];   // [Q]    f32
    float* out = (float*)d_out;

    const int B = in_sizes[0] / HDIM;
    const int ntiles = (B + TILE_ROWS - 1) / TILE_ROWS;
    int grid = ntiles < GRID_MAX ? ntiles : GRID_MAX;

    qreg_main_kernel<<<grid, NTHREADS>>>(hidden, Wm, bv, out, B);
}

// round 4
// speedup vs baseline: 1.7130x; 1.0463x over previous
#include <cuda_runtime.h>
#include <cuda_bf16.h>
#include <cstdint>

// QRegulariser: out = mean_b( 1 - prod_q cos^2( (hidden@W.T + b)_q / 2 ) )
// B=65536, H=1024, Q=8. HBM-bound: 256 MB of hidden.
//
// R4: cp.async (LDGSTS) pipeline decouples MLP from register count.
//  - h staged global->shared, 3 buffers/warp, lookahead 2 chunks, flat chunk
//    stream across tiles (no per-tile bubble). ~112KB/SM in flight >> 18KB
//    needed -> DRAM saturation (R3 was capped at 60% by 32KB reg-prefetch).
//  - RPW=7 rows/warp (acc in regs; no h regs) cuts W-LDS crossbar to ~34B/cyc.
//  - 1 CTA x 512 thr/SM, grid=148: 586 tiles/148 = 3.96 -> ~1% tail.
//  - each lane copies exactly the 16B it later reads: per-thread
//    commit_group/wait_group, no block syncs, no swizzle for h.

#define HDIM 1024
#define QDIM 8
#define RPW 7
#define WPB 16
#define NTHREADS 512
#define TILE_ROWS (RPW * WPB)        // 112
#define GRID_SMS 148
#define NCHUNK 8                      // 8 chunks of 512B per row (H=1024 f32)
#define CHUNK_BYTES 512
#define WARP_STAGE (RPW * CHUNK_BYTES)  // 3584 B per warp per buffer
#define NBUF 3
#define SW_BYTES (QDIM * HDIM * 4)    // 32 KB
#define HBUF_BYTES (WPB * NBUF * WARP_STAGE)  // 172032
#define DSMEM_BYTES (SW_BYTES + HBUF_BYTES)   // 204800

__device__ double g_partials[GRID_SMS];
__device__ unsigned int g_counter = 0;

__device__ __forceinline__ uint32_t swz(uint32_t off) {
    return off ^ ((off >> 3) & 0x70u);
}
__device__ __forceinline__ unsigned long long fma2(unsigned long long a,
                                                   unsigned long long b,
                                                   unsigned long long c) {
    unsigned long long d;
    asm("fma.rn.f32x2 %0, %1, %2, %3;" : "=l"(d) : "l"(a), "l"(b), "l"(c));
    return d;
}
__device__ __forceinline__ unsigned long long add2(unsigned long long a,
                                                   unsigned long long b) {
    unsigned long long d;
    asm("add.rn.f32x2 %0, %1, %2;" : "=l"(d) : "l"(a), "l"(b));
    return d;
}
__device__ __forceinline__ unsigned long long packff(float x) {
    unsigned long long d;
    asm("mov.b64 %0, {%1, %1};" : "=l"(d) : "f"(x));
    return d;
}
__device__ __forceinline__ float2 unpack2(unsigned long long v) {
    float2 r;
    asm("mov.b64 {%0, %1}, %2;" : "=f"(r.x), "=f"(r.y) : "l"(v));
    return r;
}
__device__ __forceinline__ void cp16(uint32_t dst_smem, const void* src) {
    asm volatile("cp.async.cg.shared.global [%0], [%1], 16;"
                 :: "r"(dst_smem), "l"(src) : "memory");
}
__device__ __forceinline__ void sts_zero16(uint32_t dst_smem) {
    asm volatile("st.shared.v4.u32 [%0], {%1, %1, %1, %1};"
                 :: "r"(dst_smem), "r"(0u) : "memory");
}
__device__ __forceinline__ void cp_commit() {
    asm volatile("cp.async.commit_group;" ::: "memory");
}
__device__ __forceinline__ void cp_wait1() {
    asm volatile("cp.async.wait_group 1;" ::: "memory");
}

__global__ __launch_bounds__(NTHREADS, 1)
void qreg_main_kernel(const float* __restrict__ hidden,
                      const float* __restrict__ Wm,
                      const float* __restrict__ bv,
                      float* __restrict__ out,
                      int B) {
    extern __shared__ __align__(128) char dsm[];
    char* sW = dsm;                   // 32 KB swizzled W^T
    char* hbuf = dsm + SW_BYTES;      // 168 KB h staging
    __shared__ float sB[QDIM];
    __shared__ double warp_sums[WPB];
    __shared__ unsigned int is_last;

    const int tid = threadIdx.x;
    const int bid = blockIdx.x;

    // Build swizzled W^T: column c gets 32B (q0..q7) at off = c*32 + q*4.
    for (int i = tid; i < QDIM * HDIM / 4; i += NTHREADS) {
        const float4 v = reinterpret_cast<const float4*>(Wm)[i];
        const int q = (i * 4) / HDIM;
        const int c = (i * 4) % HDIM;
        const float vv[4] = {v.x, v.y, v.z, v.w};
        #pragma unroll
        for (int j = 0; j < 4; ++j) {
            const uint32_t off = swz((uint32_t)(c + j) * 32u + (uint32_t)q * 4u);
            *reinterpret_cast<float*>(sW + off) = vv[j];
        }
    }
    if (tid < QDIM) sB[tid] = bv[tid];
    __syncthreads();

    const int warp = tid >> 5;
    const int lane = tid & 31;
    const int ntiles = (B + TILE_ROWS - 1) / TILE_ROWS;

    // Per-warp staging buffers (each lane only touches its own 16B column).
    const uint32_t mybuf =
        (uint32_t)__cvta_generic_to_shared(hbuf) +
        (uint32_t)warp * (NBUF * WARP_STAGE) + (uint32_t)lane * 16u;
    char* mybuf_g = hbuf + warp * (NBUF * WARP_STAGE) + lane * 16;
    const char* hbase = (const char*)hidden + (size_t)lane * 16u;

    // Count this CTA's tiles (grid-stride list: bid, bid+148, ...).
    int nmy = 0;
    for (int t = bid; t < ntiles; t += GRID_SMS) ++nmy;
    const int nchunks = nmy * NCHUNK;

    double local = 0.0;

    if (nchunks > 0) {
        // ---- issue chunk c: rows row0..row0+6, H-slice [it*128, it*128+128)
        auto issue_chunk = [&](int c) {
            const int tl = c >> 3;            // local tile index
            const int it = c & 7;             // chunk within tile
            const int t = bid + tl * GRID_SMS;
            const int row0 = t * TILE_ROWS + warp * RPW;
            const uint32_t dst = mybuf + (uint32_t)(c % NBUF) * WARP_STAGE;
            const char* src = hbase + (size_t)row0 * 4096u + (size_t)it * 512u;
            if (row0 + RPW <= B) {
                #pragma unroll
                for (int r = 0; r < RPW; ++r)
                    cp16(dst + r * 512u, src + (size_t)r * 4096u);
            } else {
                #pragma unroll
                for (int r = 0; r < RPW; ++r) {
                    if (row0 + r < B) cp16(dst + r * 512u, src + (size_t)r * 4096u);
                    else              sts_zero16(dst + r * 512u);
                }
            }
        };

        issue_chunk(0); cp_commit();
        if (nchunks > 1) issue_chunk(1);
        cp_commit();

        unsigned long long acc[RPW][4];
        #pragma unroll
        for (int r = 0; r < RPW; ++r)
            #pragma unroll
            for (int qp = 0; qp < 4; ++qp) acc[r][qp] = 0ull;

        for (int c = 0; c < nchunks; ++c) {
            cp_wait1();                       // chunk c resident
            if (c + 2 < nchunks) issue_chunk(c + 2);
            cp_commit();

            const int it = c & 7;
            const char* buf = mybuf_g + (c % NBUF) * WARP_STAGE;

            // h float4s for 7 rows (this lane's own staged 16B per row).
            float4 h[RPW];
            #pragma unroll
            for (int r = 0; r < RPW; ++r)
                h[r] = *reinterpret_cast<const float4*>(buf + r * 512);

            const int col4 = it * 32 + lane;
            #pragma unroll
            for (int j = 0; j < 4; ++j) {
                const uint32_t base = (uint32_t)col4 * 128u + (uint32_t)j * 32u;
                const ulonglong2 wA =
                    *reinterpret_cast<const ulonglong2*>(sW + swz(base));
                const ulonglong2 wB =
                    *reinterpret_cast<const ulonglong2*>(sW + swz(base + 16u));
                #pragma unroll
                for (int r = 0; r < RPW; ++r) {
                    const float* hp = &h[r].x;
                    const unsigned long long hh = packff(hp[j]);
                    acc[r][0] = fma2(hh, wA.x, acc[r][0]);
                    acc[r][1] = fma2(hh, wA.y, acc[r][1]);
                    acc[r][2] = fma2(hh, wB.x, acc[r][2]);
                    acc[r][3] = fma2(hh, wB.y, acc[r][3]);
                }
            }

            if (it == NCHUNK - 1) {
                // Tile done: butterfly-reduce accs across the warp.
                #pragma unroll
                for (int r = 0; r < RPW; ++r) {
                    #pragma unroll
                    for (int qp = 0; qp < 4; ++qp) {
                        unsigned long long v = acc[r][qp];
                        #pragma unroll
                        for (int d = 16; d > 0; d >>= 1)
                            v = add2(v, __shfl_xor_sync(0xffffffffu, v, d));
                        acc[r][qp] = v;
                    }
                }
                const int t = bid + (c >> 3) * GRID_SMS;
                const int row0 = t * TILE_ROWS + warp * RPW;
                #pragma unroll
                for (int r = 0; r < RPW; ++r) {
                    if (row0 + r >= B) continue;
                    float pr = 1.0f;
                    #pragma unroll
                    for (int qp = 0; qp < 4; ++qp) {
                        const float2 th = unpack2(acc[r][qp]);
                        const float t0 = th.x + sB[2 * qp];
                        const float t1 = th.y + sB[2 * qp + 1];
                        pr *= 0.25f * (1.0f + __cosf(t0)) * (1.0f + __cosf(t1));
                    }
                    local += (double)(1.0f - pr);
                }
                #pragma unroll
                for (int r = 0; r < RPW; ++r)
                    #pragma unroll
                    for (int qp = 0; qp < 4; ++qp) acc[r][qp] = 0ull;
            }
        }
    }

    // Block reduction of per-warp sums (lane 0 holds full sum post-butterfly;
    // epilogue ran redundantly in all lanes, any lane's `local` is the value).
    if (lane == 0) warp_sums[warp] = local;
    __syncthreads();

    if (tid == 0) {
        double s = 0.0;
        #pragma unroll
        for (int w = 0; w < WPB; ++w) s += warp_sums[w];
        g_partials[bid] = s;
        __threadfence();
        const unsigned int prev = atomicAdd(&g_counter, 1u);
        is_last = (prev == gridDim.x - 1) ? 1u : 0u;
    }
    __syncthreads();

    if (is_last) {
        __threadfence();
        const volatile double* vp = g_partials;
        double s = 0.0;
        for (int i = tid; i < (int)gridDim.x; i += NTHREADS) s += vp[i];
        #pragma unroll
        for (int d = 16; d > 0; d >>= 1)
            s += __shfl_down_sync(0xffffffffu, s, d);
        if (lane == 0) warp_sums[warp] = s;
        __syncthreads();
        if (tid == 0) {
            double tsum = 0.0;
            #pragma unroll
            for (int w = 0; w < WPB; ++w) tsum += warp_sums[w];
            out[0] = (float)(tsum / (double)B);
            g_counter = 0;  // reset for graph replay
        }
    }
}

extern "C" void kernel_launch(void* const* d_in, const int* in_sizes, int n_in,
                              void* d_out, int out_size) {
    const float* hidden = (const float*)d_in[0];   // [B, H] f32
    const float* Wm     = (const float*)d_in[1];   // [Q, H] f32
    const float* bv     = (const float*)d_in[2];   // [Q]    f32
    float* out = (float*)d_out;

    const int B = in_sizes[0] / HDIM;

    static bool attr_set = false;
    if (!attr_set) {
        cudaFuncSetAttribute(qreg_main_kernel,
                             cudaFuncAttributeMaxDynamicSharedMemorySize,
                             DSMEM_BYTES);
        attr_set = true;
    }

    qreg_main_kernel<<<GRID_SMS, NTHREADS, DSMEM_BYTES>>>(hidden, Wm, bv, out, B);
}